// round 10
// baseline (speedup 1.0000x reference)
#include <cuda_runtime.h>
#include <cuda_bf16.h>
#include <cstdint>

#define E_TOTAL   32768
#define FEAT_DIM  17
#define HID       64
#define R_DIM     768
#define OUT_PER_EDGE 2304
#define LN_EPS    1e-5f

#define EPC       128                 // edges per k2 CTA
#define NCTA      (E_TOTAL / EPC)     // 256
#define KPAD      192                 // split-K: [hi | lo | hi]
#define RB_STRIDE 132                 // rbuf row: 32 triples * 4 + pad

// A: [e][192] bf16 rows = [ahi(64) | alo(64) | ahi(64)]
__device__ __nv_bfloat16 g_abf[E_TOTAL * KPAD];
// B: [n][192] bf16 rows = [bhi(64) | bhi(64) | blo(64)]
__device__ __nv_bfloat16 g_bbf[R_DIM * KPAD];

__device__ __forceinline__ float silu_f(float x) { return x / (1.0f + __expf(-x)); }

__device__ __forceinline__ void mma_bf16(float& d0, float& d1, float& d2, float& d3,
                                         uint32_t a0, uint32_t a1, uint32_t a2, uint32_t a3,
                                         uint32_t b0, uint32_t b1) {
    asm volatile(
        "mma.sync.aligned.m16n8k16.row.col.f32.bf16.bf16.f32 "
        "{%0,%1,%2,%3}, {%4,%5,%6,%7}, {%8,%9}, {%0,%1,%2,%3};"
        : "+f"(d0), "+f"(d1), "+f"(d2), "+f"(d3)
        : "r"(a0), "r"(a1), "r"(a2), "r"(a3), "r"(b0), "r"(b1));
}

// ---------------------------------------------------------------------------
// k0: B prep. g_bbf[n][kk]: phase = kk/64 (0,1 -> hi, 2 -> lo) of W3[k][n].
// ---------------------------------------------------------------------------
__global__ __launch_bounds__(256) void k0_prep(const float* __restrict__ W3) {
    int i = blockIdx.x * 256 + threadIdx.x;
    if (i >= R_DIM * KPAD) return;
    const int n = i / KPAD, kk = i - n * KPAD;
    const int phase = kk >> 6, k = kk & 63;
    const float wv = W3[k * R_DIM + n];
    const __nv_bfloat16 hi = __float2bfloat16(wv);
    g_bbf[i] = (phase == 2) ? __float2bfloat16(wv - __bfloat162float(hi)) : hi;
}

// ---------------------------------------------------------------------------
// k1: radial MLP layers 1-2, one thread per edge, in-register LN.
// Emits g_abf rows [ahi | alo | ahi].
// ---------------------------------------------------------------------------
__global__ __launch_bounds__(256) void k1_mlp(
    const float* __restrict__ feat,
    const float* __restrict__ W1, const float* __restrict__ b1, const float* __restrict__ g1,
    const float* __restrict__ W2, const float* __restrict__ b2, const float* __restrict__ g2)
{
    __shared__ __align__(16) float sW1[FEAT_DIM * HID];
    __shared__ __align__(16) float sW2[HID * HID];
    __shared__ float sb1[HID], sg1[HID], sb2[HID], sg2[HID];
    extern __shared__ float sh_h[];   // [HID][256]

    const int t = threadIdx.x;
    for (int i = t; i < FEAT_DIM * HID; i += 256) sW1[i] = W1[i];
    for (int i = t; i < HID * HID;     i += 256) sW2[i] = W2[i];
    if (t < HID) { sb1[t] = b1[t]; sg1[t] = g1[t]; sb2[t] = b2[t]; sg2[t] = g2[t]; }
    __syncthreads();

    const int e = blockIdx.x * 256 + t;
    const float* fr = feat + (size_t)e * FEAT_DIM;

    float x[HID];
#pragma unroll
    for (int j = 0; j < HID; j++) x[j] = sb1[j];
#pragma unroll 1
    for (int c = 0; c < FEAT_DIM; c++) {
        const float fv = fr[c];
        const float4* w4 = (const float4*)(sW1 + c * HID);
#pragma unroll
        for (int j4 = 0; j4 < HID / 4; j4++) {
            float4 w = w4[j4];
            x[4*j4+0] = fmaf(fv, w.x, x[4*j4+0]);
            x[4*j4+1] = fmaf(fv, w.y, x[4*j4+1]);
            x[4*j4+2] = fmaf(fv, w.z, x[4*j4+2]);
            x[4*j4+3] = fmaf(fv, w.w, x[4*j4+3]);
        }
    }
    {
        float s = 0.f, q = 0.f;
#pragma unroll
        for (int j = 0; j < HID; j++) { x[j] = silu_f(x[j]); s += x[j]; q += x[j]*x[j]; }
        const float mu = s * (1.0f/64.0f);
        const float var = q * (1.0f/64.0f) - mu*mu;
        const float rs = rsqrtf(var + LN_EPS);
#pragma unroll
        for (int j = 0; j < HID; j++) sh_h[j * 256 + t] = (x[j] - mu) * rs * sg1[j];
    }
#pragma unroll
    for (int j = 0; j < HID; j++) x[j] = sb2[j];
#pragma unroll 1
    for (int k = 0; k < HID; k++) {
        const float hv = sh_h[k * 256 + t];
        const float4* w4 = (const float4*)(sW2 + k * HID);
#pragma unroll
        for (int j4 = 0; j4 < HID / 4; j4++) {
            float4 w = w4[j4];
            x[4*j4+0] = fmaf(hv, w.x, x[4*j4+0]);
            x[4*j4+1] = fmaf(hv, w.y, x[4*j4+1]);
            x[4*j4+2] = fmaf(hv, w.z, x[4*j4+2]);
            x[4*j4+3] = fmaf(hv, w.w, x[4*j4+3]);
        }
    }
    {
        float s = 0.f, q = 0.f;
#pragma unroll
        for (int j = 0; j < HID; j++) { x[j] = silu_f(x[j]); s += x[j]; q += x[j]*x[j]; }
        const float mu = s * (1.0f/64.0f);
        const float var = q * (1.0f/64.0f) - mu*mu;
        const float rs = rsqrtf(var + LN_EPS);
        uint32_t ph[32], pl[32];
#pragma unroll
        for (int j2 = 0; j2 < 32; j2++) {
            const float h0 = (x[2*j2]   - mu) * rs * sg2[2*j2];
            const float h1 = (x[2*j2+1] - mu) * rs * sg2[2*j2+1];
            const __nv_bfloat16 a0 = __float2bfloat16(h0), a1 = __float2bfloat16(h1);
            const __nv_bfloat16 c0 = __float2bfloat16(h0 - __bfloat162float(a0));
            const __nv_bfloat16 c1 = __float2bfloat16(h1 - __bfloat162float(a1));
            ph[j2] = (uint32_t)__bfloat16_as_ushort(a0) | ((uint32_t)__bfloat16_as_ushort(a1) << 16);
            pl[j2] = (uint32_t)__bfloat16_as_ushort(c0) | ((uint32_t)__bfloat16_as_ushort(c1) << 16);
        }
        uint4* dst = (uint4*)(g_abf + (size_t)e * KPAD);
#pragma unroll
        for (int q4 = 0; q4 < 8; q4++)
            dst[q4] = make_uint4(ph[4*q4], ph[4*q4+1], ph[4*q4+2], ph[4*q4+3]);
#pragma unroll
        for (int q4 = 0; q4 < 8; q4++)
            dst[8 + q4] = make_uint4(pl[4*q4], pl[4*q4+1], pl[4*q4+2], pl[4*q4+3]);
#pragma unroll
        for (int q4 = 0; q4 < 8; q4++)
            dst[16 + q4] = make_uint4(ph[4*q4], ph[4*q4+1], ph[4*q4+2], ph[4*q4+3]);
    }
}

// ---------------------------------------------------------------------------
// k2: mma.sync bf16 split-K GEMM (r = h2@W3 + b3) fused with tensor product.
// CTA = 128 edges, 8 warps; warp w owns edges [16w,16w+16) with A frags in
// regs for the whole kernel. 8 col-chunks of 96 (= 32 triples = 2 o-values):
// GEMM -> bias -> stage triples into padded rbuf -> float4 TP -> STG.128.
// ---------------------------------------------------------------------------
__global__ __launch_bounds__(256, 2) void k2_mma_tp(
    const float* __restrict__ basis,
    const float* __restrict__ b3,
    float* __restrict__ out)
{
    extern __shared__ float smem[];
    float* rbuf = smem;                       // [128][RB_STRIDE] 67.6 KB
    float* sbas = rbuf + 128 * RB_STRIDE;     // [128][40]        20.5 KB
    float* sb3  = sbas + 128 * 40;            // [768]             3 KB

    const int t = threadIdx.x;
    const int w = t >> 5, l = t & 31;
    const int g = l >> 2, tig = l & 3;
    const int e0 = blockIdx.x * EPC;

    // stage basis + b3
    for (int i = t; i < EPC * 27; i += 256) {
        const int e = i / 27, r = i - 27 * e;
        const int dd = r / 9, rr = r - 9 * dd;
        sbas[e * 40 + dd * 12 + rr] = basis[(size_t)(e0 + e) * 27 + r];
    }
    for (int i = t; i < R_DIM; i += 256) sb3[i] = b3[i];

    // A fragments for this warp's 16 edges: 12 k-frags x 4 regs
    uint32_t af[12][4];
    {
        const char* ab = (const char*)(g_abf + (size_t)(e0 + 16 * w) * KPAD);
#pragma unroll
        for (int kf = 0; kf < 12; kf++) {
            const int ko = kf * 32 + 4 * tig;
            af[kf][0] = *(const uint32_t*)(ab + (size_t)g * 384 + ko);
            af[kf][1] = *(const uint32_t*)(ab + (size_t)(g + 8) * 384 + ko);
            af[kf][2] = *(const uint32_t*)(ab + (size_t)g * 384 + ko + 16);
            af[kf][3] = *(const uint32_t*)(ab + (size_t)(g + 8) * 384 + ko + 16);
        }
    }
    __syncthreads();

#pragma unroll 1
    for (int c = 0; c < 8; c++) {
        // GEMM: 12 n-tiles, 2 at a time for ILP
#pragma unroll 1
        for (int j = 0; j < 12; j += 2) {
            const int n0 = c * 96 + j * 8;
            const char* br0 = (const char*)(g_bbf + (size_t)(n0 + g) * KPAD);
            const char* br1 = br0 + 8 * KPAD * 2;
            float d0 = 0.f, d1 = 0.f, d2 = 0.f, d3 = 0.f;
            float e0r = 0.f, e1r = 0.f, e2r = 0.f, e3r = 0.f;
#pragma unroll
            for (int kf = 0; kf < 12; kf++) {
                const int ko = kf * 32 + 4 * tig;
                const uint32_t b00 = *(const uint32_t*)(br0 + ko);
                const uint32_t b01 = *(const uint32_t*)(br0 + ko + 16);
                const uint32_t b10 = *(const uint32_t*)(br1 + ko);
                const uint32_t b11 = *(const uint32_t*)(br1 + ko + 16);
                mma_bf16(d0, d1, d2, d3, af[kf][0], af[kf][1], af[kf][2], af[kf][3], b00, b01);
                mma_bf16(e0r, e1r, e2r, e3r, af[kf][0], af[kf][1], af[kf][2], af[kf][3], b10, b11);
            }
            // bias + stage into rbuf (triple-padded)
            const int eL = 16 * w + g;
#pragma unroll
            for (int tt = 0; tt < 2; tt++) {
                const int cc0 = (j + tt) * 8 + 2 * tig;
                const int cc1 = cc0 + 1;
                const float bs0 = sb3[c * 96 + cc0];
                const float bs1 = sb3[c * 96 + cc1];
                const int a0 = (cc0 / 3) * 4 + (cc0 % 3);
                const int a1 = (cc1 / 3) * 4 + (cc1 % 3);
                const float v0 = (tt ? e0r : d0) + bs0;
                const float v1 = (tt ? e1r : d1) + bs1;
                const float v2 = (tt ? e2r : d2) + bs0;
                const float v3 = (tt ? e3r : d3) + bs1;
                rbuf[eL * RB_STRIDE + a0] = v0;
                rbuf[eL * RB_STRIDE + a1] = v1;
                rbuf[(eL + 8) * RB_STRIDE + a0] = v2;
                rbuf[(eL + 8) * RB_STRIDE + a1] = v3;
            }
        }
        __syncthreads();

        // TP phase: 128 edges x 288 out floats (o in {2c, 2c+1}) = 9216 float4
#pragma unroll 1
        for (int it = 0; it < 36; it++) {
            const int idx = it * 256 + t;
            const int e = idx / 72;
            const int p72 = idx - 72 * e;
            const int oL = p72 / 36;
            const int rem = p72 - 36 * oL;
            const int dd = rem / 12;
            const int pos = rem - 12 * dd;
            const int s4 = 4 * pos;
            const int i0 = s4 / 3;
            const int m0 = s4 - 3 * i0;
            const float* rrow = rbuf + e * RB_STRIDE + (oL * 16 + i0) * 4;
            const float4 ra  = *(const float4*)(rrow);
            const float4 rbt = *(const float4*)(rrow + 4);
            const float* B = sbas + e * 40 + dd * 12;
            const float4 b04 = *(const float4*)(B);
            const float4 b14 = *(const float4*)(B + 4);
            const float  b8  = B[8];
            const float da0 = ra.x * b04.x + ra.y * b04.y + ra.z * b04.z;
            const float da1 = ra.x * b04.w + ra.y * b14.x + ra.z * b14.y;
            const float da2 = ra.x * b14.z + ra.y * b14.w + ra.z * b8;
            const float db0 = rbt.x * b04.x + rbt.y * b04.y + rbt.z * b04.z;
            const float db1 = rbt.x * b04.w + rbt.y * b14.x + rbt.z * b14.y;
            const float db2 = rbt.x * b14.z + rbt.y * b14.w + rbt.z * b8;
            float4 ov;
            ov.x = (m0 == 0) ? da0 : ((m0 == 1) ? da1 : da2);
            ov.y = (m0 == 0) ? da1 : ((m0 == 1) ? da2 : db0);
            ov.z = (m0 == 0) ? da2 : ((m0 == 1) ? db0 : db1);
            ov.w = (m0 == 0) ? db0 : ((m0 == 1) ? db1 : db2);
            *(float4*)(out + (size_t)(e0 + e) * OUT_PER_EDGE + (2 * c + oL) * 144 + dd * 48 + s4) = ov;
        }
        __syncthreads();
    }
}

// ---------------------------------------------------------------------------
extern "C" void kernel_launch(void* const* d_in, const int* in_sizes, int n_in,
                              void* d_out, int out_size)
{
    const float* feat  = (const float*)d_in[0];
    const float* basis = (const float*)d_in[1];
    const float* W1    = (const float*)d_in[2];
    const float* b1    = (const float*)d_in[3];
    const float* g1    = (const float*)d_in[4];
    const float* W2    = (const float*)d_in[5];
    const float* b2    = (const float*)d_in[6];
    const float* g2    = (const float*)d_in[7];
    const float* W3    = (const float*)d_in[8];
    const float* b3    = (const float*)d_in[9];
    float* out = (float*)d_out;

    const int k1_dyn = HID * 256 * sizeof(float);   // 64 KB
    const int k2_dyn = (128 * RB_STRIDE + 128 * 40 + R_DIM) * sizeof(float);  // ~91 KB
    cudaFuncSetAttribute(k1_mlp, cudaFuncAttributeMaxDynamicSharedMemorySize, k1_dyn);
    cudaFuncSetAttribute(k2_mma_tp, cudaFuncAttributeMaxDynamicSharedMemorySize, k2_dyn);

    k0_prep<<<(R_DIM * KPAD + 255) / 256, 256>>>(W3);
    k1_mlp<<<E_TOTAL / 256, 256, k1_dyn>>>(feat, W1, b1, g1, W2, b2, g2);
    k2_mma_tp<<<NCTA, 256, k2_dyn>>>(basis, b3, out);
}

// round 13
// speedup vs baseline: 1.7653x; 1.7653x over previous
#include <cuda_runtime.h>
#include <cuda_bf16.h>
#include <cstdint>

#define E_TOTAL   32768
#define FEAT_DIM  17
#define HID       64
#define R_DIM     768
#define OUT_PER_EDGE 2304
#define LN_EPS    1e-5f

#define EPC       128                 // edges per k2 CTA
#define NCTA      (E_TOTAL / EPC)     // 256
#define KPAD      192                 // split-K: [hi | lo | hi]
#define CCOLS     48                  // cols per chunk (= 16 triples = 1 o)
#define NCH       (R_DIM / CCOLS)     // 16
#define BST       200                 // smem B row stride (bf16 elems)
#define RBS       68                  // rbuf row stride (floats)

// A: [e][192] bf16 rows = [ahi(64) | alo(64) | ahi(64)]
__device__ __nv_bfloat16 g_abf[E_TOTAL * KPAD];
// B: [n][192] bf16 rows = [bhi(64) | bhi(64) | blo(64)]
__device__ __nv_bfloat16 g_bbf[R_DIM * KPAD];

__device__ __forceinline__ float silu_f(float x) { return x / (1.0f + __expf(-x)); }

__device__ __forceinline__ void mma_bf16(float& d0, float& d1, float& d2, float& d3,
                                         uint32_t a0, uint32_t a1, uint32_t a2, uint32_t a3,
                                         uint32_t b0, uint32_t b1) {
    asm volatile(
        "mma.sync.aligned.m16n8k16.row.col.f32.bf16.bf16.f32 "
        "{%0,%1,%2,%3}, {%4,%5,%6,%7}, {%8,%9}, {%0,%1,%2,%3};"
        : "+f"(d0), "+f"(d1), "+f"(d2), "+f"(d3)
        : "r"(a0), "r"(a1), "r"(a2), "r"(a3), "r"(b0), "r"(b1));
}

// ---------------------------------------------------------------------------
// k0: B prep. g_bbf[n][kk]: phase = kk/64 (0,1 -> hi, 2 -> lo) of W3[k][n].
// ---------------------------------------------------------------------------
__global__ __launch_bounds__(256) void k0_prep(const float* __restrict__ W3) {
    int i = blockIdx.x * 256 + threadIdx.x;
    if (i >= R_DIM * KPAD) return;
    const int n = i / KPAD, kk = i - n * KPAD;
    const int phase = kk >> 6, k = kk & 63;
    const float wv = W3[k * R_DIM + n];
    const __nv_bfloat16 hi = __float2bfloat16(wv);
    g_bbf[i] = (phase == 2) ? __float2bfloat16(wv - __bfloat162float(hi)) : hi;
}

// ---------------------------------------------------------------------------
// k1: radial MLP layers 1-2, one thread per edge, in-register LN.
// Emits g_abf rows [ahi | alo | ahi].
// ---------------------------------------------------------------------------
__global__ __launch_bounds__(256) void k1_mlp(
    const float* __restrict__ feat,
    const float* __restrict__ W1, const float* __restrict__ b1, const float* __restrict__ g1,
    const float* __restrict__ W2, const float* __restrict__ b2, const float* __restrict__ g2)
{
    __shared__ __align__(16) float sW1[FEAT_DIM * HID];
    __shared__ __align__(16) float sW2[HID * HID];
    __shared__ float sb1[HID], sg1[HID], sb2[HID], sg2[HID];
    extern __shared__ float sh_h[];   // [HID][256]

    const int t = threadIdx.x;
    for (int i = t; i < FEAT_DIM * HID; i += 256) sW1[i] = W1[i];
    for (int i = t; i < HID * HID;     i += 256) sW2[i] = W2[i];
    if (t < HID) { sb1[t] = b1[t]; sg1[t] = g1[t]; sb2[t] = b2[t]; sg2[t] = g2[t]; }
    __syncthreads();

    const int e = blockIdx.x * 256 + t;
    const float* fr = feat + (size_t)e * FEAT_DIM;

    float x[HID];
#pragma unroll
    for (int j = 0; j < HID; j++) x[j] = sb1[j];
#pragma unroll 1
    for (int c = 0; c < FEAT_DIM; c++) {
        const float fv = fr[c];
        const float4* w4 = (const float4*)(sW1 + c * HID);
#pragma unroll
        for (int j4 = 0; j4 < HID / 4; j4++) {
            float4 w = w4[j4];
            x[4*j4+0] = fmaf(fv, w.x, x[4*j4+0]);
            x[4*j4+1] = fmaf(fv, w.y, x[4*j4+1]);
            x[4*j4+2] = fmaf(fv, w.z, x[4*j4+2]);
            x[4*j4+3] = fmaf(fv, w.w, x[4*j4+3]);
        }
    }
    {
        float s = 0.f, q = 0.f;
#pragma unroll
        for (int j = 0; j < HID; j++) { x[j] = silu_f(x[j]); s += x[j]; q += x[j]*x[j]; }
        const float mu = s * (1.0f/64.0f);
        const float var = q * (1.0f/64.0f) - mu*mu;
        const float rs = rsqrtf(var + LN_EPS);
#pragma unroll
        for (int j = 0; j < HID; j++) sh_h[j * 256 + t] = (x[j] - mu) * rs * sg1[j];
    }
#pragma unroll
    for (int j = 0; j < HID; j++) x[j] = sb2[j];
#pragma unroll 1
    for (int k = 0; k < HID; k++) {
        const float hv = sh_h[k * 256 + t];
        const float4* w4 = (const float4*)(sW2 + k * HID);
#pragma unroll
        for (int j4 = 0; j4 < HID / 4; j4++) {
            float4 w = w4[j4];
            x[4*j4+0] = fmaf(hv, w.x, x[4*j4+0]);
            x[4*j4+1] = fmaf(hv, w.y, x[4*j4+1]);
            x[4*j4+2] = fmaf(hv, w.z, x[4*j4+2]);
            x[4*j4+3] = fmaf(hv, w.w, x[4*j4+3]);
        }
    }
    {
        float s = 0.f, q = 0.f;
#pragma unroll
        for (int j = 0; j < HID; j++) { x[j] = silu_f(x[j]); s += x[j]; q += x[j]*x[j]; }
        const float mu = s * (1.0f/64.0f);
        const float var = q * (1.0f/64.0f) - mu*mu;
        const float rs = rsqrtf(var + LN_EPS);
        uint32_t ph[32], pl[32];
#pragma unroll
        for (int j2 = 0; j2 < 32; j2++) {
            const float h0 = (x[2*j2]   - mu) * rs * sg2[2*j2];
            const float h1 = (x[2*j2+1] - mu) * rs * sg2[2*j2+1];
            const __nv_bfloat16 a0 = __float2bfloat16(h0), a1 = __float2bfloat16(h1);
            const __nv_bfloat16 c0 = __float2bfloat16(h0 - __bfloat162float(a0));
            const __nv_bfloat16 c1 = __float2bfloat16(h1 - __bfloat162float(a1));
            ph[j2] = (uint32_t)__bfloat16_as_ushort(a0) | ((uint32_t)__bfloat16_as_ushort(a1) << 16);
            pl[j2] = (uint32_t)__bfloat16_as_ushort(c0) | ((uint32_t)__bfloat16_as_ushort(c1) << 16);
        }
        uint4* dst = (uint4*)(g_abf + (size_t)e * KPAD);
#pragma unroll
        for (int q4 = 0; q4 < 8; q4++)
            dst[q4] = make_uint4(ph[4*q4], ph[4*q4+1], ph[4*q4+2], ph[4*q4+3]);
#pragma unroll
        for (int q4 = 0; q4 < 8; q4++)
            dst[8 + q4] = make_uint4(pl[4*q4], pl[4*q4+1], pl[4*q4+2], pl[4*q4+3]);
#pragma unroll
        for (int q4 = 0; q4 < 8; q4++)
            dst[16 + q4] = make_uint4(ph[4*q4], ph[4*q4+1], ph[4*q4+2], ph[4*q4+3]);
    }
}

// ---------------------------------------------------------------------------
// k2: mma.sync bf16 split-K GEMM + fused tensor product.
// CTA = 128 edges, 8 warps, warp w owns edges [16w,16w+16), A frags resident
// in 48 regs. 16 chunks of 48 cols: stage B[48x192] into smem (stride 200,
// conflict-free frag loads) -> HMMA -> bias -> rbuf triples -> float4 TP.
// ---------------------------------------------------------------------------
__global__ __launch_bounds__(256, 2) void k2_mma_tp(
    const float* __restrict__ basis,
    const float* __restrict__ b3,
    float* __restrict__ out)
{
    extern __shared__ float smem[];
    float* rbuf = smem;                               // [128][68]  34.8 KB
    float* sbas = rbuf + EPC * RBS;                   // [128][40]  20.5 KB
    float* sb3  = sbas + EPC * 40;                    // [768]       3 KB
    __nv_bfloat16* sB = (__nv_bfloat16*)(sb3 + R_DIM);// [48][200]  19.2 KB

    const int t = threadIdx.x;
    const int w = t >> 5, l = t & 31;
    const int g = l >> 2, tig = l & 3;
    const int e0 = blockIdx.x * EPC;

    // stage basis + b3
    for (int i = t; i < EPC * 27; i += 256) {
        const int e = i / 27, r = i - 27 * e;
        const int dd = r / 9, rr = r - 9 * dd;
        sbas[e * 40 + dd * 12 + rr] = basis[(size_t)(e0 + e) * 27 + r];
    }
    for (int i = t; i < R_DIM; i += 256) sb3[i] = b3[i];

    // A fragments for this warp's 16 edges: 12 k-frags x 4 regs
    uint32_t af[12][4];
    {
        const char* ab = (const char*)(g_abf + (size_t)(e0 + 16 * w) * KPAD);
#pragma unroll
        for (int kf = 0; kf < 12; kf++) {
            const int ko = kf * 32 + 4 * tig;
            af[kf][0] = *(const uint32_t*)(ab + (size_t)g * 384 + ko);
            af[kf][1] = *(const uint32_t*)(ab + (size_t)(g + 8) * 384 + ko);
            af[kf][2] = *(const uint32_t*)(ab + (size_t)g * 384 + ko + 16);
            af[kf][3] = *(const uint32_t*)(ab + (size_t)(g + 8) * 384 + ko + 16);
        }
    }

#pragma unroll 1
    for (int c = 0; c < NCH; c++) {
        // ---- stage B chunk: 48 rows x 192 bf16 -> sB stride 200 ----
        // (previous chunk's B readers are past: mma phase ended at last sync)
        for (int i = t; i < 48 * 24; i += 256) {
            const int row = i / 24, q = i - 24 * row;
            *(uint4*)(sB + row * BST + q * 8) =
                *(const uint4*)(g_bbf + (size_t)(c * CCOLS + row) * KPAD + q * 8);
        }
        __syncthreads();

        // ---- GEMM: 6 n-tiles, 2 at a time ----
#pragma unroll 1
        for (int j = 0; j < 6; j += 2) {
            const __nv_bfloat16* br0 = sB + (j * 8 + g) * BST;
            const __nv_bfloat16* br1 = br0 + 8 * BST;
            float d0 = 0.f, d1 = 0.f, d2 = 0.f, d3 = 0.f;
            float f0 = 0.f, f1 = 0.f, f2 = 0.f, f3 = 0.f;
#pragma unroll
            for (int kf = 0; kf < 12; kf++) {
                const int ke = kf * 16 + 2 * tig;
                const uint32_t b00 = *(const uint32_t*)(br0 + ke);
                const uint32_t b01 = *(const uint32_t*)(br0 + ke + 8);
                const uint32_t b10 = *(const uint32_t*)(br1 + ke);
                const uint32_t b11 = *(const uint32_t*)(br1 + ke + 8);
                mma_bf16(d0, d1, d2, d3, af[kf][0], af[kf][1], af[kf][2], af[kf][3], b00, b01);
                mma_bf16(f0, f1, f2, f3, af[kf][0], af[kf][1], af[kf][2], af[kf][3], b10, b11);
            }
            // bias + stage triples into rbuf
            const int eL = 16 * w + g;
#pragma unroll
            for (int tt = 0; tt < 2; tt++) {
                const int cc0 = (j + tt) * 8 + 2 * tig;
                const int cc1 = cc0 + 1;
                const float bs0 = sb3[c * CCOLS + cc0];
                const float bs1 = sb3[c * CCOLS + cc1];
                const int a0 = (cc0 / 3) * 4 + (cc0 % 3);
                const int a1 = (cc1 / 3) * 4 + (cc1 % 3);
                rbuf[eL * RBS + a0]       = (tt ? f0 : d0) + bs0;
                rbuf[eL * RBS + a1]       = (tt ? f1 : d1) + bs1;
                rbuf[(eL + 8) * RBS + a0] = (tt ? f2 : d2) + bs0;
                rbuf[(eL + 8) * RBS + a1] = (tt ? f3 : d3) + bs1;
            }
        }
        __syncthreads();

        // ---- TP phase: 128 edges x 144 floats (o = c) = 4608 float4 ----
#pragma unroll 1
        for (int it = 0; it < 18; it++) {
            const int idx = it * 256 + t;
            const int e = idx / 36;
            const int rem = idx - 36 * e;
            const int dd = rem / 12;
            const int pos = rem - 12 * dd;
            const int s4 = 4 * pos;
            const int i0 = s4 / 3;
            const int m0 = s4 - 3 * i0;
            const float* rrow = rbuf + e * RBS + i0 * 4;
            const float4 ra  = *(const float4*)(rrow);
            const float4 rbt = *(const float4*)(rrow + 4);
            const float* B = sbas + e * 40 + dd * 12;
            const float4 b04 = *(const float4*)(B);
            const float4 b14 = *(const float4*)(B + 4);
            const float  b8  = B[8];
            const float da0 = ra.x * b04.x + ra.y * b04.y + ra.z * b04.z;
            const float da1 = ra.x * b04.w + ra.y * b14.x + ra.z * b14.y;
            const float da2 = ra.x * b14.z + ra.y * b14.w + ra.z * b8;
            const float db0 = rbt.x * b04.x + rbt.y * b04.y + rbt.z * b04.z;
            const float db1 = rbt.x * b04.w + rbt.y * b14.x + rbt.z * b14.y;
            const float db2 = rbt.x * b14.z + rbt.y * b14.w + rbt.z * b8;
            float4 ov;
            ov.x = (m0 == 0) ? da0 : ((m0 == 1) ? da1 : da2);
            ov.y = (m0 == 0) ? da1 : ((m0 == 1) ? da2 : db0);
            ov.z = (m0 == 0) ? da2 : ((m0 == 1) ? db0 : db1);
            ov.w = (m0 == 0) ? db0 : ((m0 == 1) ? db1 : db2);
            *(float4*)(out + (size_t)(e0 + e) * OUT_PER_EDGE + c * 144 + dd * 48 + s4) = ov;
        }
        __syncthreads();
    }
}

// ---------------------------------------------------------------------------
extern "C" void kernel_launch(void* const* d_in, const int* in_sizes, int n_in,
                              void* d_out, int out_size)
{
    const float* feat  = (const float*)d_in[0];
    const float* basis = (const float*)d_in[1];
    const float* W1    = (const float*)d_in[2];
    const float* b1    = (const float*)d_in[3];
    const float* g1    = (const float*)d_in[4];
    const float* W2    = (const float*)d_in[5];
    const float* b2    = (const float*)d_in[6];
    const float* g2    = (const float*)d_in[7];
    const float* W3    = (const float*)d_in[8];
    const float* b3    = (const float*)d_in[9];
    float* out = (float*)d_out;

    const int k1_dyn = HID * 256 * sizeof(float);   // 64 KB
    const int k2_dyn = (EPC * RBS + EPC * 40 + R_DIM) * sizeof(float)
                     + 48 * BST * sizeof(__nv_bfloat16);  // ~77.6 KB
    cudaFuncSetAttribute(k1_mlp, cudaFuncAttributeMaxDynamicSharedMemorySize, k1_dyn);
    cudaFuncSetAttribute(k2_mma_tp, cudaFuncAttributeMaxDynamicSharedMemorySize, k2_dyn);

    k0_prep<<<(R_DIM * KPAD + 255) / 256, 256>>>(W3);
    k1_mlp<<<E_TOTAL / 256, 256, k1_dyn>>>(feat, W1, b1, g1, W2, b2, g2);
    k2_mma_tp<<<NCTA, 256, k2_dyn>>>(basis, b3, out);
}

// round 14
// speedup vs baseline: 1.8476x; 1.0466x over previous
#include <cuda_runtime.h>
#include <cuda_bf16.h>
#include <cstdint>

#define E_TOTAL   32768
#define FEAT_DIM  17
#define HID       64
#define R_DIM     768
#define OUT_PER_EDGE 2304
#define LN_EPS    1e-5f

#define EPC       128                 // edges per k2 CTA
#define NCTA      (E_TOTAL / EPC)     // 256
#define KPAD      192                 // split-K: [hi | lo | hi]
#define CCOLS     48                  // cols per chunk (= 16 triples = 1 o)
#define NCH       (R_DIM / CCOLS)     // 16
#define BST       200                 // smem B row stride (bf16 elems)
#define RBS       68                  // rbuf row stride (floats)
#define SA_ST     100                 // sA row stride (u32)
#define H_ST      66                  // h row stride (floats)

// byte offsets in dynamic smem (main-loop layout)
#define OFF_RBUF  0                   // [128][68] f32      34816 B
#define OFF_SBAS  34816               // [128][40] f32      20480 B
#define OFF_SB3   55296               // [768] f32           3072 B
#define OFF_SB0   58368               // [48][200] bf16     19200 B
#define OFF_SB1   77568               // [48][200] bf16     19200 B
#define SM_TOTAL  96768
// prologue aliases: h [0,33792) ; sA [0,51200) ; weights [55296,77056)
#define OFF_PW1   55296
#define OFF_PW2   (OFF_PW1 + FEAT_DIM * HID * 4)   // 59648
#define OFF_PB    (OFF_PW2 + HID * HID * 4)        // 76032: b1|g1|b2|g2

// B: [n][192] bf16 rows = [bhi(64) | bhi(64) | blo(64)]
__device__ __nv_bfloat16 g_bbf[R_DIM * KPAD];

__device__ __forceinline__ float silu_f(float x) { return x / (1.0f + __expf(-x)); }

__device__ __forceinline__ void mma_bf16(float& d0, float& d1, float& d2, float& d3,
                                         uint32_t a0, uint32_t a1, uint32_t a2, uint32_t a3,
                                         uint32_t b0, uint32_t b1) {
    asm volatile(
        "mma.sync.aligned.m16n8k16.row.col.f32.bf16.bf16.f32 "
        "{%0,%1,%2,%3}, {%4,%5,%6,%7}, {%8,%9}, {%0,%1,%2,%3};"
        : "+f"(d0), "+f"(d1), "+f"(d2), "+f"(d3)
        : "r"(a0), "r"(a1), "r"(a2), "r"(a3), "r"(b0), "r"(b1));
}

// ---------------------------------------------------------------------------
// k0: B prep. g_bbf[n][kk]: phase = kk/64 (0,1 -> hi, 2 -> lo) of W3[k][n].
// ---------------------------------------------------------------------------
__global__ __launch_bounds__(256) void k0_prep(const float* __restrict__ W3) {
    int i = blockIdx.x * 256 + threadIdx.x;
    if (i >= R_DIM * KPAD) return;
    const int n = i / KPAD, kk = i - n * KPAD;
    const int phase = kk >> 6, k = kk & 63;
    const float wv = W3[k * R_DIM + n];
    const __nv_bfloat16 hi = __float2bfloat16(wv);
    g_bbf[i] = (phase == 2) ? __float2bfloat16(wv - __bfloat162float(hi)) : hi;
}

// ---------------------------------------------------------------------------
// k2: fused radial-MLP prologue + mma.sync split-K GEMM + tensor product.
// CTA = 128 edges. Prologue: 2 threads/edge compute layers 1-2 (pair LN via
// shfl), emit A-rows [hi|lo|hi] to smem sA (stride 100 u32), load A frags to
// regs. Main loop: 16 chunks of 48 cols, double-buffered smem B with register
// prefetch, HMMA -> bias -> rbuf triples -> float4 TP -> STG.128.
// ---------------------------------------------------------------------------
__global__ __launch_bounds__(256, 2) void k2_fused(
    const float* __restrict__ feat,
    const float* __restrict__ basis,
    const float* __restrict__ W1, const float* __restrict__ b1, const float* __restrict__ g1,
    const float* __restrict__ W2, const float* __restrict__ b2, const float* __restrict__ g2,
    const float* __restrict__ b3,
    float* __restrict__ out)
{
    extern __shared__ __align__(16) char smem[];
    float* rbuf = (float*)(smem + OFF_RBUF);
    float* sbas = (float*)(smem + OFF_SBAS);
    float* sb3  = (float*)(smem + OFF_SB3);
    __nv_bfloat16* sB0 = (__nv_bfloat16*)(smem + OFF_SB0);
    __nv_bfloat16* sB1 = (__nv_bfloat16*)(smem + OFF_SB1);

    const int t = threadIdx.x;
    const int w = t >> 5, l = t & 31;
    const int g = l >> 2, tig = l & 3;
    const int e0 = blockIdx.x * EPC;

    // ================= prologue: radial MLP for this CTA's 128 edges =======
    {
        float* sW1p = (float*)(smem + OFF_PW1);
        float* sW2p = (float*)(smem + OFF_PW2);
        float* pb   = (float*)(smem + OFF_PB);   // [b1|g1|b2|g2] x64
        for (int i = t; i < FEAT_DIM * HID; i += 256) sW1p[i] = W1[i];
        for (int i = t; i < HID * HID;     i += 256) sW2p[i] = W2[i];
        if (t < HID) { pb[t] = b1[t]; pb[64 + t] = g1[t]; pb[128 + t] = b2[t]; pb[192 + t] = g2[t]; }
        __syncthreads();

        const int eL = t >> 1, half = t & 1, jb = 32 * half;
        const float* fr = feat + (size_t)(e0 + eL) * FEAT_DIM;
        float* hrow = (float*)smem + eL * H_ST;

        float x[32];
#pragma unroll
        for (int jj = 0; jj < 32; jj++) x[jj] = pb[jb + jj];
#pragma unroll 1
        for (int c = 0; c < FEAT_DIM; c++) {
            const float fv = fr[c];
            const float4* w4 = (const float4*)(sW1p + c * HID + jb);
#pragma unroll
            for (int j4 = 0; j4 < 8; j4++) {
                float4 wv = w4[j4];
                x[4*j4+0] = fmaf(fv, wv.x, x[4*j4+0]);
                x[4*j4+1] = fmaf(fv, wv.y, x[4*j4+1]);
                x[4*j4+2] = fmaf(fv, wv.z, x[4*j4+2]);
                x[4*j4+3] = fmaf(fv, wv.w, x[4*j4+3]);
            }
        }
        {
            float s = 0.f, q = 0.f;
#pragma unroll
            for (int jj = 0; jj < 32; jj++) { x[jj] = silu_f(x[jj]); s += x[jj]; q += x[jj]*x[jj]; }
            s += __shfl_xor_sync(0xffffffffu, s, 1);
            q += __shfl_xor_sync(0xffffffffu, q, 1);
            const float mu = s * (1.0f/64.0f);
            const float var = q * (1.0f/64.0f) - mu*mu;
            const float rs = rsqrtf(var + LN_EPS);
#pragma unroll
            for (int jj = 0; jj < 32; jj++)
                hrow[jb + jj] = (x[jj] - mu) * rs * pb[64 + jb + jj];
        }
        __syncwarp();

        // layer 2
#pragma unroll
        for (int jj = 0; jj < 32; jj++) x[jj] = pb[128 + jb + jj];
#pragma unroll 1
        for (int k = 0; k < HID; k++) {
            const float hv = hrow[k];
            const float4* w4 = (const float4*)(sW2p + k * HID + jb);
#pragma unroll
            for (int j4 = 0; j4 < 8; j4++) {
                float4 wv = w4[j4];
                x[4*j4+0] = fmaf(hv, wv.x, x[4*j4+0]);
                x[4*j4+1] = fmaf(hv, wv.y, x[4*j4+1]);
                x[4*j4+2] = fmaf(hv, wv.z, x[4*j4+2]);
                x[4*j4+3] = fmaf(hv, wv.w, x[4*j4+3]);
            }
        }
        float s = 0.f, q = 0.f;
#pragma unroll
        for (int jj = 0; jj < 32; jj++) { x[jj] = silu_f(x[jj]); s += x[jj]; q += x[jj]*x[jj]; }
        s += __shfl_xor_sync(0xffffffffu, s, 1);
        q += __shfl_xor_sync(0xffffffffu, q, 1);
        const float mu = s * (1.0f/64.0f);
        const float var = q * (1.0f/64.0f) - mu*mu;
        const float rs = rsqrtf(var + LN_EPS);

        uint32_t hi16[16], lo16[16];
#pragma unroll
        for (int p = 0; p < 16; p++) {
            const float h0 = (x[2*p]   - mu) * rs * pb[192 + jb + 2*p];
            const float h1 = (x[2*p+1] - mu) * rs * pb[192 + jb + 2*p+1];
            const __nv_bfloat16 a0 = __float2bfloat16(h0), a1 = __float2bfloat16(h1);
            const __nv_bfloat16 c0 = __float2bfloat16(h0 - __bfloat162float(a0));
            const __nv_bfloat16 c1 = __float2bfloat16(h1 - __bfloat162float(a1));
            hi16[p] = (uint32_t)__bfloat16_as_ushort(a0) | ((uint32_t)__bfloat16_as_ushort(a1) << 16);
            lo16[p] = (uint32_t)__bfloat16_as_ushort(c0) | ((uint32_t)__bfloat16_as_ushort(c1) << 16);
        }
        __syncthreads();   // all reads of hrow/sW2p done before sA overwrite

        uint32_t* sA = (uint32_t*)smem;
        uint32_t* row = sA + eL * SA_ST;
#pragma unroll
        for (int p = 0; p < 16; p++) row[16 * half + p] = hi16[p];
#pragma unroll
        for (int p = 0; p < 16; p++) row[32 + 16 * half + p] = lo16[p];
#pragma unroll
        for (int p = 0; p < 16; p++) row[64 + 16 * half + p] = hi16[p];
    }
    __syncthreads();

    // A fragments: 12 k-frags x 4 regs from sA (conflict-free: 4g+8kf+tig)
    uint32_t af[12][4];
    {
        const uint32_t* sA = (const uint32_t*)smem;
        const int r0 = (16 * w + g) * SA_ST;
        const int r1 = (16 * w + g + 8) * SA_ST;
#pragma unroll
        for (int kf = 0; kf < 12; kf++) {
            const int ko = kf * 8 + tig;
            af[kf][0] = sA[r0 + ko];
            af[kf][1] = sA[r1 + ko];
            af[kf][2] = sA[r0 + ko + 4];
            af[kf][3] = sA[r1 + ko + 4];
        }
    }
    __syncthreads();

    // stage basis + b3 + B chunk 0
    for (int i = t; i < EPC * 27; i += 256) {
        const int e = i / 27, r = i - 27 * e;
        const int dd = r / 9, rr = r - 9 * dd;
        sbas[e * 40 + dd * 12 + rr] = basis[(size_t)(e0 + e) * 27 + r];
    }
    for (int i = t; i < R_DIM; i += 256) sb3[i] = b3[i];
    for (int i = t; i < 48 * 24; i += 256) {
        const int row = i / 24, q = i - 24 * row;
        *(uint4*)(sB0 + row * BST + q * 8) = *(const uint4*)(g_bbf + (size_t)row * KPAD + q * 8);
    }
    __syncthreads();

    // ================= main loop: 16 chunks ================================
#pragma unroll 1
    for (int c = 0; c < NCH; c++) {
        const __nv_bfloat16* sBc = (c & 1) ? sB1 : sB0;
        __nv_bfloat16*       sBn = (c & 1) ? sB0 : sB1;
        const bool hasn = (c + 1) < NCH;

        // prefetch next B chunk into regs
        uint4 pf[5];
        if (hasn) {
            const uint4* gb4 = (const uint4*)(g_bbf + (size_t)(c + 1) * CCOLS * KPAD);
#pragma unroll
            for (int q4 = 0; q4 < 4; q4++) pf[q4] = gb4[q4 * 256 + t];
            if (t < 128) pf[4] = gb4[1024 + t];
        }

        // GEMM: 6 n-tiles, 2 at a time
#pragma unroll 1
        for (int j = 0; j < 6; j += 2) {
            const __nv_bfloat16* br0 = sBc + (j * 8 + g) * BST;
            const __nv_bfloat16* br1 = br0 + 8 * BST;
            float d0 = 0.f, d1 = 0.f, d2 = 0.f, d3 = 0.f;
            float f0 = 0.f, f1 = 0.f, f2 = 0.f, f3 = 0.f;
#pragma unroll
            for (int kf = 0; kf < 12; kf++) {
                const int ke = kf * 16 + 2 * tig;
                const uint32_t b00 = *(const uint32_t*)(br0 + ke);
                const uint32_t b01 = *(const uint32_t*)(br0 + ke + 8);
                const uint32_t b10 = *(const uint32_t*)(br1 + ke);
                const uint32_t b11 = *(const uint32_t*)(br1 + ke + 8);
                mma_bf16(d0, d1, d2, d3, af[kf][0], af[kf][1], af[kf][2], af[kf][3], b00, b01);
                mma_bf16(f0, f1, f2, f3, af[kf][0], af[kf][1], af[kf][2], af[kf][3], b10, b11);
            }
            const int eL = 16 * w + g;
#pragma unroll
            for (int tt = 0; tt < 2; tt++) {
                const int cc0 = (j + tt) * 8 + 2 * tig;
                const int cc1 = cc0 + 1;
                const float bs0 = sb3[c * CCOLS + cc0];
                const float bs1 = sb3[c * CCOLS + cc1];
                const int a0 = (cc0 / 3) * 4 + (cc0 % 3);
                const int a1 = (cc1 / 3) * 4 + (cc1 % 3);
                rbuf[eL * RBS + a0]       = (tt ? f0 : d0) + bs0;
                rbuf[eL * RBS + a1]       = (tt ? f1 : d1) + bs1;
                rbuf[(eL + 8) * RBS + a0] = (tt ? f2 : d2) + bs0;
                rbuf[(eL + 8) * RBS + a1] = (tt ? f3 : d3) + bs1;
            }
        }
        __syncthreads();   // rbuf ready; sBn free

        // commit prefetched B to the other buffer
        if (hasn) {
#pragma unroll
            for (int q4 = 0; q4 < 4; q4++) {
                const int i = q4 * 256 + t;
                const int row = i / 24, q = i - 24 * row;
                *(uint4*)(sBn + row * BST + q * 8) = pf[q4];
            }
            if (t < 128) {
                const int i = 1024 + t;
                const int row = i / 24, q = i - 24 * row;
                *(uint4*)(sBn + row * BST + q * 8) = pf[4];
            }
        }

        // TP phase: 128 edges x 144 floats (o = c) = 4608 float4
#pragma unroll 1
        for (int it = 0; it < 18; it++) {
            const int idx = it * 256 + t;
            const int e = idx / 36;
            const int rem = idx - 36 * e;
            const int dd = rem / 12;
            const int pos = rem - 12 * dd;
            const int s4 = 4 * pos;
            const int i0 = s4 / 3;
            const int m0 = s4 - 3 * i0;
            const float* rrow = rbuf + e * RBS + i0 * 4;
            const float4 ra  = *(const float4*)(rrow);
            const float4 rbt = *(const float4*)(rrow + 4);
            const float* B = sbas + e * 40 + dd * 12;
            const float4 b04 = *(const float4*)(B);
            const float4 b14 = *(const float4*)(B + 4);
            const float  b8  = B[8];
            const float da0 = ra.x * b04.x + ra.y * b04.y + ra.z * b04.z;
            const float da1 = ra.x * b04.w + ra.y * b14.x + ra.z * b14.y;
            const float da2 = ra.x * b14.z + ra.y * b14.w + ra.z * b8;
            const float db0 = rbt.x * b04.x + rbt.y * b04.y + rbt.z * b04.z;
            const float db1 = rbt.x * b04.w + rbt.y * b14.x + rbt.z * b14.y;
            const float db2 = rbt.x * b14.z + rbt.y * b14.w + rbt.z * b8;
            float4 ov;
            ov.x = (m0 == 0) ? da0 : ((m0 == 1) ? da1 : da2);
            ov.y = (m0 == 0) ? da1 : ((m0 == 1) ? da2 : db0);
            ov.z = (m0 == 0) ? da2 : ((m0 == 1) ? db0 : db1);
            ov.w = (m0 == 0) ? db0 : ((m0 == 1) ? db1 : db2);
            *(float4*)(out + (size_t)(e0 + e) * OUT_PER_EDGE + c * 144 + dd * 48 + s4) = ov;
        }
        __syncthreads();
    }
}

// ---------------------------------------------------------------------------
extern "C" void kernel_launch(void* const* d_in, const int* in_sizes, int n_in,
                              void* d_out, int out_size)
{
    const float* feat  = (const float*)d_in[0];
    const float* basis = (const float*)d_in[1];
    const float* W1    = (const float*)d_in[2];
    const float* b1    = (const float*)d_in[3];
    const float* g1    = (const float*)d_in[4];
    const float* W2    = (const float*)d_in[5];
    const float* b2    = (const float*)d_in[6];
    const float* g2    = (const float*)d_in[7];
    const float* W3    = (const float*)d_in[8];
    const float* b3    = (const float*)d_in[9];
    float* out = (float*)d_out;

    cudaFuncSetAttribute(k2_fused, cudaFuncAttributeMaxDynamicSharedMemorySize, SM_TOTAL);

    k0_prep<<<(R_DIM * KPAD + 255) / 256, 256>>>(W3);
    k2_fused<<<NCTA, 256, SM_TOTAL>>>(feat, basis, W1, b1, g1, W2, b2, g2, b3, out);
}